// round 14
// baseline (speedup 1.0000x reference)
#include <cuda_runtime.h>
#include <cstdint>

// ============================================================
// BinarizeConv2d: out = conv3x3(sign(x), sign(mix(W))) * scale * alpha
// Implicit GEMM, mma.sync m16n8k32 s8s8s32 (exact for ±1), sm_100.
// R14 = R13 GEMM with table-free epilogue (per-thread offset is
//       constant: r = tid&127) + prep_x at 2 h-rows per block.
// ============================================================

#define B_   32
#define CIN  256
#define COUT 256
#define H_   56
#define W_   56
#define HP   58
#define WP   58
#define HW   3136      // 56*56

// int8 encodings of {+1,-1,0}: 0x01, 0xFF, 0x00
__device__ uint8_t g_xb[(size_t)B_ * HP * WP * CIN];  // sign(x), NHWC padded (borders stay 0)
__device__ uint8_t g_wb[9 * COUT * CIN];              // sign(real_w) [tap][co][ci]
__device__ float   g_sa[COUT];                        // alpha * scale

// ---------------- PTX helpers ----------------
__device__ __forceinline__ uint32_t smem_u32(const void* p) {
    uint32_t a;
    asm("{ .reg .u64 t; cvta.to.shared.u64 t, %1; cvt.u32.u64 %0, t; }" : "=r"(a) : "l"(p));
    return a;
}
#define CP16(d, s)   asm volatile("cp.async.cg.shared.global [%0], [%1], 16;" :: "r"(d), "l"(s) : "memory")
#define CP_COMMIT()  asm volatile("cp.async.commit_group;" ::: "memory")
#define CP_WAIT(n)   asm volatile("cp.async.wait_group %0;" :: "n"(n) : "memory")

#define LDSM4(r, a)                                                          \
    asm volatile("ldmatrix.sync.aligned.m8n8.x4.shared.b16 {%0,%1,%2,%3}, [%4];" \
        : "=r"((r)[0]), "=r"((r)[1]), "=r"((r)[2]), "=r"((r)[3]) : "r"(a))

#define MMAI(d, a, b0, b1)                                                   \
    asm volatile("mma.sync.aligned.m16n8k32.row.col.s32.s8.s8.s32 "          \
        "{%0,%1,%2,%3}, {%4,%5,%6,%7}, {%8,%9}, {%0,%1,%2,%3};"              \
        : "+r"((d)[0]), "+r"((d)[1]), "+r"((d)[2]), "+r"((d)[3])             \
        : "r"((a)[0]), "r"((a)[1]), "r"((a)[2]), "r"((a)[3]),                \
          "r"(b0), "r"(b1))

__device__ __forceinline__ uint8_t sign_s8(float v) {
    return (v > 0.f) ? 0x01 : ((v < 0.f) ? 0xFF : 0x00);
}

// ---------------- merged prep kernel ----------------
// blocks [0,256):       weight mix/sign/scale (co = blockIdx.x), smem-staged
// blocks [256,256+896): binarize x for one (b, 2 h-rows): all 256 ci,
//                       coalesced contiguous row writes into g_xb
#define XSTRIDE 272    // smem row stride: 16B-aligned, <=2-way bank conflict

__global__ void prep_all(const float* __restrict__ Wt, const float* __restrict__ RV,
                         const float* __restrict__ alpha, const float* __restrict__ x) {
    // Single pool, branches overlay their views:
    //   w-branch: ws = 4*2304 floats (36864B) + red = 256 floats (1024B) = 37888B
    //   x-branch: sb = 2 * 56*272 bytes (30464B)
    __shared__ __align__(16) char pool[4 * 2304 * 4 + 256 * 4];   // 37888B
    const int tid = threadIdx.x;
    if (blockIdx.x < COUT) {
        float* ws  = (float*)pool;                   // [4*2304]
        float* red = (float*)(pool + 4 * 2304 * 4);  // [256]
        const int co = blockIdx.x, ci = tid;
        const size_t ks = (size_t)COUT * CIN * 9;
#pragma unroll
        for (int u = 0; u < 9; u++) {
            int idx = tid + 256 * u;                 // 0..2303
            const float* src = Wt + (size_t)co * 2304 + idx;
            ws[idx]        = src[0];
            ws[idx + 2304] = src[ks];
            ws[idx + 4608] = src[2 * ks];
            ws[idx + 6912] = src[3 * ks];
        }
        __syncthreads();
        const float r0 = RV[0], r1 = RV[1], r2 = RV[2], r3 = RV[3];
        float acc = 0.f;
#pragma unroll
        for (int t = 0; t < 9; t++) {
            int idx = ci * 9 + t;
            float rw = r0 * ws[idx] + r1 * ws[idx + 2304] +
                       r2 * ws[idx + 4608] + r3 * ws[idx + 6912];
            acc += fabsf(rw);
            g_wb[((size_t)t * COUT + co) * CIN + ci] = sign_s8(rw);
        }
        red[ci] = acc;
        __syncthreads();
        for (int st = 128; st > 0; st >>= 1) {
            if (ci < st) red[ci] += red[ci + st];
            __syncthreads();
        }
        if (ci == 0) g_sa[co] = alpha[co] * (red[0] * (1.0f / 2304.0f));
    } else {
        uint8_t* sb = (uint8_t*)pool;              // [2][56 * XSTRIDE] = 30464B
        const int id = blockIdx.x - COUT;          // 0..895
        const int h0 = (id % 28) * 2;
        const int b  = id / 28;
        const float* xp = x + (size_t)b * CIN * HW;
        // i = ci*28 + hi*14 + j : 256 ci x 2 h x 14 float4 = 7168 loads,
        // runs of 14 consecutive threads cover one (ci,hi) row contiguously.
        for (int i = tid; i < 7168; i += 256) {
            int ci = i / 28;
            int t2 = i - ci * 28;
            int hi = t2 / 14;
            int j  = t2 - hi * 14;
            float4 v = *reinterpret_cast<const float4*>(
                xp + (size_t)ci * HW + (size_t)(h0 + hi) * W_ + 4 * j);
            int base = hi * (56 * XSTRIDE) + (4 * j) * XSTRIDE + ci;
            sb[base]               = sign_s8(v.x);
            sb[base + XSTRIDE]     = sign_s8(v.y);
            sb[base + 2 * XSTRIDE] = sign_s8(v.z);
            sb[base + 3 * XSTRIDE] = sign_s8(v.w);
        }
        __syncthreads();
        // two contiguous 56*256 = 14336B destination rows (w=1..56 interior)
#pragma unroll
        for (int hi = 0; hi < 2; hi++) {
            uint8_t* dst = g_xb + (((size_t)b * HP + (h0 + hi + 1)) * WP + 1) * CIN;
            const uint8_t* src = sb + hi * (56 * XSTRIDE);
            for (int u = tid; u < 896; u += 256) {     // 896 uint4
                int w = u >> 4, s = (u & 15) * 16;
                *reinterpret_cast<uint4*>(dst + w * 256 + s) =
                    *reinterpret_cast<const uint4*>(src + w * XSTRIDE + s);
            }
        }
    }
}

// ---------------- main GEMM kernel ----------------
#define NSTG     3
#define A_BYTES  16384                 // 128 M-rows x 128B
#define STG      32768                 // A(16K) + B(16K)
#define GSMEM    (NSTG * STG)          // 98304 B -> 2 CTAs/SM
#define NCHUNK   18                    // 9 taps x 2 ci-chunks of 128

__global__ void __launch_bounds__(256, 2) bconv_gemm(float* __restrict__ out) {
    extern __shared__ char smem[];
    const uint32_t sbase = smem_u32(smem);
    const int tid  = threadIdx.x;
    const int warp = tid >> 5, lane = tid & 31;
    const int mw = warp >> 1;          // 0..3: M rows 32*mw..+31
    const int nw = warp & 1;           // 0..1: N cols 64*nw..+63
    const int bidx = blockIdx.x;
    const int co0  = (bidx & 1) * 128;
    const int m0   = (bidx >> 1) << 7;   // 784*128 = 100352 exact

    const int seg = tid & 7;
    const int rb  = tid >> 3;

    int aoff[4];
#pragma unroll
    for (int k = 0; k < 4; k++) {
        int m = m0 + rb + 32 * k;
        int ib  = m / HW;
        int rem = m - ib * HW;
        int h = rem / W_, w = rem - h * W_;
        aoff[k] = ((ib * HP + h) * WP + w) * CIN + seg * 16;
    }
    int boff[4];
#pragma unroll
    for (int k = 0; k < 4; k++) boff[k] = (co0 + rb + 32 * k) * CIN + seg * 16;
    const uint32_t dstb = rb * 128 + ((seg * 16) ^ ((rb & 7) << 4));

    const int rlo   = lane & 15;
    const int khalf = (lane >> 4) << 4;
    const int swz   = (rlo & 7) << 4;

    int d[2][8][4];
#pragma unroll
    for (int mi = 0; mi < 2; mi++)
#pragma unroll
        for (int ni = 0; ni < 8; ni++)
#pragma unroll
            for (int j = 0; j < 4; j++) d[mi][ni][j] = 0;

    auto load_chunk = [&](int chunk, int stage) {
        const int t  = chunk >> 1;
        const int cc = (chunk & 1) << 7;
        const int kh = t / 3, kw = t - kh * 3;
        const int toffA = (kh * WP + kw) * CIN + cc;
        const int toffB = t * (COUT * CIN) + cc;
        const uint32_t stgA = sbase + stage * STG + dstb;
        const uint32_t stgB = stgA + A_BYTES;
#pragma unroll
        for (int k = 0; k < 4; k++)
            CP16(stgA + k * 4096, (const char*)g_xb + aoff[k] + toffA);
#pragma unroll
        for (int k = 0; k < 4; k++)
            CP16(stgB + k * 4096, (const char*)g_wb + boff[k] + toffB);
    };

    load_chunk(0, 0); CP_COMMIT();
    load_chunk(1, 1); CP_COMMIT();

    const int rowA0 = 32 * mw + rlo;
    const int rowB0 = 64 * nw + rlo;

    int stage = 2;
    for (int i = 0; i < NCHUNK; i++) {
        CP_WAIT(1);
        __syncthreads();
        if (i + 2 < NCHUNK) load_chunk(i + 2, stage);
        CP_COMMIT();

        const int cur = (stage == 2) ? 0 : stage + 1;   // = i % 3
        stage = cur;
        const uint32_t stgA = sbase + cur * STG;
        const uint32_t stgB = stgA + A_BYTES;
#pragma unroll
        for (int ks = 0; ks < 4; ks++) {
            const int kb = ks * 32 + khalf;
            uint32_t a[2][4], bf[4][4];
            LDSM4(a[0], stgA + rowA0 * 128 + (kb ^ swz));
            LDSM4(a[1], stgA + (rowA0 + 16) * 128 + (kb ^ swz));
#pragma unroll
            for (int np = 0; np < 4; np++)
                LDSM4(bf[np], stgB + (rowB0 + 16 * np) * 128 + (kb ^ swz));
#pragma unroll
            for (int np = 0; np < 4; np++) {
                MMAI(d[0][2 * np],     a[0], bf[np][0], bf[np][2]);
                MMAI(d[0][2 * np + 1], a[0], bf[np][1], bf[np][3]);
                MMAI(d[1][2 * np],     a[1], bf[np][0], bf[np][2]);
                MMAI(d[1][2 * np + 1], a[1], bf[np][1], bf[np][3]);
            }
        }
    }

    CP_WAIT(0);
    __syncthreads();

    // ---------------- epilogue (table-free) ----------------
    // Store index u = tid + 256*it -> r = u&127 = tid&127 (CONSTANT per
    // thread), cl = (tid>>7) + 2*it. Per-thread output offset computed once.
    int* buf = (int*)smem;                         // 64 cl x 128 rows = 32KB
    const int r   = tid & 127;
    const int clb = tid >> 7;
    int soff;
    {
        int m   = m0 + r;
        int ib  = m / HW;
        int rem = m - ib * HW;
        soff = ib * (COUT * HW) + rem;
    }
    const int q  = lane & 3;
    const int rr = lane >> 2;
#pragma unroll 1
    for (int hh = 0; hh < 2; hh++) {
        if (nw == hh) {
#pragma unroll
            for (int mi = 0; mi < 2; mi++)
#pragma unroll
                for (int ni = 0; ni < 8; ni++) {
                    int cl  = 8 * ni + 2 * q;
                    int row = 32 * mw + 16 * mi + rr;
                    buf[cl * 128 + row]           = d[mi][ni][0];
                    buf[(cl + 1) * 128 + row]     = d[mi][ni][1];
                    buf[cl * 128 + row + 8]       = d[mi][ni][2];
                    buf[(cl + 1) * 128 + row + 8] = d[mi][ni][3];
                }
        }
        __syncthreads();
#pragma unroll 4
        for (int it = 0; it < 32; it++) {
            int cl = clb + 2 * it;
            int co = co0 + hh * 64 + cl;
            out[soff + co * HW] = (float)buf[cl * 128 + r] * __ldg(&g_sa[co]);
        }
        __syncthreads();
    }
}

// ---------------- launch ----------------
extern "C" void kernel_launch(void* const* d_in, const int* in_sizes, int n_in,
                              void* d_out, int out_size) {
    const float* x     = (const float*)d_in[0];  // [32,256,56,56]
    const float* wts   = (const float*)d_in[1];  // [4,256,256,3,3]
    const float* rv    = (const float*)d_in[2];  // [5]
    const float* alpha = (const float*)d_in[3];  // [256]
    float* out = (float*)d_out;

    cudaFuncSetAttribute(bconv_gemm, cudaFuncAttributeMaxDynamicSharedMemorySize, GSMEM);

    prep_all<<<COUT + B_ * (H_ / 2), 256>>>(wts, rv, alpha, x);
    bconv_gemm<<<784 * 2, 256, GSMEM>>>(out);
}

// round 15
// speedup vs baseline: 1.0680x; 1.0680x over previous
#include <cuda_runtime.h>
#include <cstdint>

// ============================================================
// BinarizeConv2d: out = conv3x3(sign(x), sign(mix(W))) * scale * alpha
// Implicit GEMM, mma.sync m16n8k32 s8s8s32 (exact for ±1), sm_100.
// R15 = R13 GEMM (+R14's neutral table-free epilogue), prep SPLIT
//       into prep_w / prep_x so x-blocks don't reserve the 37KB
//       union footprint (R13 merged prep capped x-occupancy; R14's
//       2-rows/block cut block count and regressed).
// ============================================================

#define B_   32
#define CIN  256
#define COUT 256
#define H_   56
#define W_   56
#define HP   58
#define WP   58
#define HW   3136      // 56*56

// int8 encodings of {+1,-1,0}: 0x01, 0xFF, 0x00
__device__ uint8_t g_xb[(size_t)B_ * HP * WP * CIN];  // sign(x), NHWC padded (borders stay 0)
__device__ uint8_t g_wb[9 * COUT * CIN];              // sign(real_w) [tap][co][ci]
__device__ float   g_sa[COUT];                        // alpha * scale

// ---------------- PTX helpers ----------------
__device__ __forceinline__ uint32_t smem_u32(const void* p) {
    uint32_t a;
    asm("{ .reg .u64 t; cvta.to.shared.u64 t, %1; cvt.u32.u64 %0, t; }" : "=r"(a) : "l"(p));
    return a;
}
#define CP16(d, s)   asm volatile("cp.async.cg.shared.global [%0], [%1], 16;" :: "r"(d), "l"(s) : "memory")
#define CP_COMMIT()  asm volatile("cp.async.commit_group;" ::: "memory")
#define CP_WAIT(n)   asm volatile("cp.async.wait_group %0;" :: "n"(n) : "memory")

#define LDSM4(r, a)                                                          \
    asm volatile("ldmatrix.sync.aligned.m8n8.x4.shared.b16 {%0,%1,%2,%3}, [%4];" \
        : "=r"((r)[0]), "=r"((r)[1]), "=r"((r)[2]), "=r"((r)[3]) : "r"(a))

#define MMAI(d, a, b0, b1)                                                   \
    asm volatile("mma.sync.aligned.m16n8k32.row.col.s32.s8.s8.s32 "          \
        "{%0,%1,%2,%3}, {%4,%5,%6,%7}, {%8,%9}, {%0,%1,%2,%3};"              \
        : "+r"((d)[0]), "+r"((d)[1]), "+r"((d)[2]), "+r"((d)[3])             \
        : "r"((a)[0]), "r"((a)[1]), "r"((a)[2]), "r"((a)[3]),                \
          "r"(b0), "r"(b1))

__device__ __forceinline__ uint8_t sign_s8(float v) {
    return (v > 0.f) ? 0x01 : ((v < 0.f) ? 0xFF : 0x00);
}

// ---------------- prep kernel 1: weights (256 blocks, 37.9KB smem) ----------------
__global__ void prep_w(const float* __restrict__ Wt, const float* __restrict__ RV,
                       const float* __restrict__ alpha) {
    __shared__ float ws[4 * 2304];   // 36864B
    __shared__ float red[256];
    const int tid = threadIdx.x;
    const int co = blockIdx.x, ci = tid;
    const size_t ks = (size_t)COUT * CIN * 9;
#pragma unroll
    for (int u = 0; u < 9; u++) {
        int idx = tid + 256 * u;                 // 0..2303
        const float* src = Wt + (size_t)co * 2304 + idx;
        ws[idx]        = src[0];
        ws[idx + 2304] = src[ks];
        ws[idx + 4608] = src[2 * ks];
        ws[idx + 6912] = src[3 * ks];
    }
    __syncthreads();
    const float r0 = RV[0], r1 = RV[1], r2 = RV[2], r3 = RV[3];
    float acc = 0.f;
#pragma unroll
    for (int t = 0; t < 9; t++) {
        int idx = ci * 9 + t;
        float rw = r0 * ws[idx] + r1 * ws[idx + 2304] +
                   r2 * ws[idx + 4608] + r3 * ws[idx + 6912];
        acc += fabsf(rw);
        g_wb[((size_t)t * COUT + co) * CIN + ci] = sign_s8(rw);
    }
    red[ci] = acc;
    __syncthreads();
    for (int st = 128; st > 0; st >>= 1) {
        if (ci < st) red[ci] += red[ci + st];
        __syncthreads();
    }
    if (ci == 0) g_sa[co] = alpha[co] * (red[0] * (1.0f / 2304.0f));
}

// ---------------- prep kernel 2: binarize x (1792 blocks, 15.2KB smem) ----------------
#define XSTRIDE 272    // smem row stride: 16B-aligned, <=2-way bank conflict

__global__ void prep_x(const float* __restrict__ x) {
    __shared__ __align__(16) uint8_t sb[56 * XSTRIDE];  // 15232B
    const int tid = threadIdx.x;
    const int id  = blockIdx.x;                  // 0..1791
    const int h   = id % H_;
    const int b   = id / H_;
    const float* xp = x + (size_t)b * CIN * HW + (size_t)h * W_;
    // 256 ci x 14 float4 = 3584 loads; runs of 14 consecutive threads
    // cover one ci's 224B contiguously.
    for (int i = tid; i < 3584; i += 256) {
        int ci = i / 14;
        int j  = i - ci * 14;
        float4 v = *reinterpret_cast<const float4*>(xp + (size_t)ci * HW + 4 * j);
        int base = (4 * j) * XSTRIDE + ci;
        sb[base]               = sign_s8(v.x);
        sb[base + XSTRIDE]     = sign_s8(v.y);
        sb[base + 2 * XSTRIDE] = sign_s8(v.z);
        sb[base + 3 * XSTRIDE] = sign_s8(v.w);
    }
    __syncthreads();
    // contiguous 56*256 = 14336B destination row (w=1..56 interior)
    uint8_t* dst = g_xb + (((size_t)b * HP + (h + 1)) * WP + 1) * CIN;
    for (int u = tid; u < 896; u += 256) {       // 896 uint4
        int w = u >> 4, s = (u & 15) * 16;
        *reinterpret_cast<uint4*>(dst + w * 256 + s) =
            *reinterpret_cast<const uint4*>(sb + w * XSTRIDE + s);
    }
}

// ---------------- main GEMM kernel ----------------
#define NSTG     3
#define A_BYTES  16384                 // 128 M-rows x 128B
#define STG      32768                 // A(16K) + B(16K)
#define GSMEM    (NSTG * STG)          // 98304 B -> 2 CTAs/SM
#define NCHUNK   18                    // 9 taps x 2 ci-chunks of 128

__global__ void __launch_bounds__(256, 2) bconv_gemm(float* __restrict__ out) {
    extern __shared__ char smem[];
    const uint32_t sbase = smem_u32(smem);
    const int tid  = threadIdx.x;
    const int warp = tid >> 5, lane = tid & 31;
    const int mw = warp >> 1;          // 0..3: M rows 32*mw..+31
    const int nw = warp & 1;           // 0..1: N cols 64*nw..+63
    const int bidx = blockIdx.x;
    const int co0  = (bidx & 1) * 128;
    const int m0   = (bidx >> 1) << 7;   // 784*128 = 100352 exact

    const int seg = tid & 7;
    const int rb  = tid >> 3;

    int aoff[4];
#pragma unroll
    for (int k = 0; k < 4; k++) {
        int m = m0 + rb + 32 * k;
        int ib  = m / HW;
        int rem = m - ib * HW;
        int h = rem / W_, w = rem - h * W_;
        aoff[k] = ((ib * HP + h) * WP + w) * CIN + seg * 16;
    }
    int boff[4];
#pragma unroll
    for (int k = 0; k < 4; k++) boff[k] = (co0 + rb + 32 * k) * CIN + seg * 16;
    const uint32_t dstb = rb * 128 + ((seg * 16) ^ ((rb & 7) << 4));

    const int rlo   = lane & 15;
    const int khalf = (lane >> 4) << 4;
    const int swz   = (rlo & 7) << 4;

    int d[2][8][4];
#pragma unroll
    for (int mi = 0; mi < 2; mi++)
#pragma unroll
        for (int ni = 0; ni < 8; ni++)
#pragma unroll
            for (int j = 0; j < 4; j++) d[mi][ni][j] = 0;

    auto load_chunk = [&](int chunk, int stage) {
        const int t  = chunk >> 1;
        const int cc = (chunk & 1) << 7;
        const int kh = t / 3, kw = t - kh * 3;
        const int toffA = (kh * WP + kw) * CIN + cc;
        const int toffB = t * (COUT * CIN) + cc;
        const uint32_t stgA = sbase + stage * STG + dstb;
        const uint32_t stgB = stgA + A_BYTES;
#pragma unroll
        for (int k = 0; k < 4; k++)
            CP16(stgA + k * 4096, (const char*)g_xb + aoff[k] + toffA);
#pragma unroll
        for (int k = 0; k < 4; k++)
            CP16(stgB + k * 4096, (const char*)g_wb + boff[k] + toffB);
    };

    load_chunk(0, 0); CP_COMMIT();
    load_chunk(1, 1); CP_COMMIT();

    const int rowA0 = 32 * mw + rlo;
    const int rowB0 = 64 * nw + rlo;

    int stage = 2;
    for (int i = 0; i < NCHUNK; i++) {
        CP_WAIT(1);
        __syncthreads();
        if (i + 2 < NCHUNK) load_chunk(i + 2, stage);
        CP_COMMIT();

        const int cur = (stage == 2) ? 0 : stage + 1;   // = i % 3
        stage = cur;
        const uint32_t stgA = sbase + cur * STG;
        const uint32_t stgB = stgA + A_BYTES;
#pragma unroll
        for (int ks = 0; ks < 4; ks++) {
            const int kb = ks * 32 + khalf;
            uint32_t a[2][4], bf[4][4];
            LDSM4(a[0], stgA + rowA0 * 128 + (kb ^ swz));
            LDSM4(a[1], stgA + (rowA0 + 16) * 128 + (kb ^ swz));
#pragma unroll
            for (int np = 0; np < 4; np++)
                LDSM4(bf[np], stgB + (rowB0 + 16 * np) * 128 + (kb ^ swz));
#pragma unroll
            for (int np = 0; np < 4; np++) {
                MMAI(d[0][2 * np],     a[0], bf[np][0], bf[np][2]);
                MMAI(d[0][2 * np + 1], a[0], bf[np][1], bf[np][3]);
                MMAI(d[1][2 * np],     a[1], bf[np][0], bf[np][2]);
                MMAI(d[1][2 * np + 1], a[1], bf[np][1], bf[np][3]);
            }
        }
    }

    CP_WAIT(0);
    __syncthreads();

    // ---------------- epilogue (table-free) ----------------
    int* buf = (int*)smem;                         // 64 cl x 128 rows = 32KB
    const int r   = tid & 127;
    const int clb = tid >> 7;
    int soff;
    {
        int m   = m0 + r;
        int ib  = m / HW;
        int rem = m - ib * HW;
        soff = ib * (COUT * HW) + rem;
    }
    const int q  = lane & 3;
    const int rr = lane >> 2;
#pragma unroll 1
    for (int hh = 0; hh < 2; hh++) {
        if (nw == hh) {
#pragma unroll
            for (int mi = 0; mi < 2; mi++)
#pragma unroll
                for (int ni = 0; ni < 8; ni++) {
                    int cl  = 8 * ni + 2 * q;
                    int row = 32 * mw + 16 * mi + rr;
                    buf[cl * 128 + row]           = d[mi][ni][0];
                    buf[(cl + 1) * 128 + row]     = d[mi][ni][1];
                    buf[cl * 128 + row + 8]       = d[mi][ni][2];
                    buf[(cl + 1) * 128 + row + 8] = d[mi][ni][3];
                }
        }
        __syncthreads();
#pragma unroll 4
        for (int it = 0; it < 32; it++) {
            int cl = clb + 2 * it;
            int co = co0 + hh * 64 + cl;
            out[soff + co * HW] = (float)buf[cl * 128 + r] * __ldg(&g_sa[co]);
        }
        __syncthreads();
    }
}

// ---------------- launch ----------------
extern "C" void kernel_launch(void* const* d_in, const int* in_sizes, int n_in,
                              void* d_out, int out_size) {
    const float* x     = (const float*)d_in[0];  // [32,256,56,56]
    const float* wts   = (const float*)d_in[1];  // [4,256,256,3,3]
    const float* rv    = (const float*)d_in[2];  // [5]
    const float* alpha = (const float*)d_in[3];  // [256]
    float* out = (float*)d_out;

    cudaFuncSetAttribute(bconv_gemm, cudaFuncAttributeMaxDynamicSharedMemorySize, GSMEM);

    prep_x<<<B_ * H_, 256>>>(x);
    prep_w<<<COUT, 256>>>(wts, rv, alpha);
    bconv_gemm<<<784 * 2, 256, GSMEM>>>(out);
}

// round 16
// speedup vs baseline: 1.1069x; 1.0364x over previous
#include <cuda_runtime.h>
#include <cstdint>

// ============================================================
// BinarizeConv2d: out = conv3x3(sign(x), sign(mix(W))) * scale * alpha
// Implicit GEMM, mma.sync m16n8k32 s8s8s32 (exact for ±1), sm_100.
// R16 = R15 with prep_x restructured: 4ci x 4w blocks per thread,
//       packed STS.32 (4x fewer stores) + 16B-block XOR swizzle
//       (7-way -> ~2-way store conflicts, conflict-free reads).
//       GEMM + prep_w unchanged from R15 champion.
// ============================================================

#define B_   32
#define CIN  256
#define COUT 256
#define H_   56
#define W_   56
#define HP   58
#define WP   58
#define HW   3136      // 56*56

// int8 encodings of {+1,-1,0}: 0x01, 0xFF, 0x00
__device__ uint8_t g_xb[(size_t)B_ * HP * WP * CIN];  // sign(x), NHWC padded (borders stay 0)
__device__ uint8_t g_wb[9 * COUT * CIN];              // sign(real_w) [tap][co][ci]
__device__ float   g_sa[COUT];                        // alpha * scale

// ---------------- PTX helpers ----------------
__device__ __forceinline__ uint32_t smem_u32(const void* p) {
    uint32_t a;
    asm("{ .reg .u64 t; cvta.to.shared.u64 t, %1; cvt.u32.u64 %0, t; }" : "=r"(a) : "l"(p));
    return a;
}
#define CP16(d, s)   asm volatile("cp.async.cg.shared.global [%0], [%1], 16;" :: "r"(d), "l"(s) : "memory")
#define CP_COMMIT()  asm volatile("cp.async.commit_group;" ::: "memory")
#define CP_WAIT(n)   asm volatile("cp.async.wait_group %0;" :: "n"(n) : "memory")

#define LDSM4(r, a)                                                          \
    asm volatile("ldmatrix.sync.aligned.m8n8.x4.shared.b16 {%0,%1,%2,%3}, [%4];" \
        : "=r"((r)[0]), "=r"((r)[1]), "=r"((r)[2]), "=r"((r)[3]) : "r"(a))

#define MMAI(d, a, b0, b1)                                                   \
    asm volatile("mma.sync.aligned.m16n8k32.row.col.s32.s8.s8.s32 "          \
        "{%0,%1,%2,%3}, {%4,%5,%6,%7}, {%8,%9}, {%0,%1,%2,%3};"              \
        : "+r"((d)[0]), "+r"((d)[1]), "+r"((d)[2]), "+r"((d)[3])             \
        : "r"((a)[0]), "r"((a)[1]), "r"((a)[2]), "r"((a)[3]),                \
          "r"(b0), "r"(b1))

__device__ __forceinline__ uint8_t sign_s8(float v) {
    return (v > 0.f) ? 0x01 : ((v < 0.f) ? 0xFF : 0x00);
}
__device__ __forceinline__ uint32_t sign4(float a, float b, float c, float d) {
    return (uint32_t)sign_s8(a) | ((uint32_t)sign_s8(b) << 8) |
           ((uint32_t)sign_s8(c) << 16) | ((uint32_t)sign_s8(d) << 24);
}

// ---------------- prep kernel 1: weights (256 blocks, 37.9KB smem) ----------------
__global__ void prep_w(const float* __restrict__ Wt, const float* __restrict__ RV,
                       const float* __restrict__ alpha) {
    __shared__ float ws[4 * 2304];   // 36864B
    __shared__ float red[256];
    const int tid = threadIdx.x;
    const int co = blockIdx.x, ci = tid;
    const size_t ks = (size_t)COUT * CIN * 9;
#pragma unroll
    for (int u = 0; u < 9; u++) {
        int idx = tid + 256 * u;                 // 0..2303
        const float* src = Wt + (size_t)co * 2304 + idx;
        ws[idx]        = src[0];
        ws[idx + 2304] = src[ks];
        ws[idx + 4608] = src[2 * ks];
        ws[idx + 6912] = src[3 * ks];
    }
    __syncthreads();
    const float r0 = RV[0], r1 = RV[1], r2 = RV[2], r3 = RV[3];
    float acc = 0.f;
#pragma unroll
    for (int t = 0; t < 9; t++) {
        int idx = ci * 9 + t;
        float rw = r0 * ws[idx] + r1 * ws[idx + 2304] +
                   r2 * ws[idx + 4608] + r3 * ws[idx + 6912];
        acc += fabsf(rw);
        g_wb[((size_t)t * COUT + co) * CIN + ci] = sign_s8(rw);
    }
    red[ci] = acc;
    __syncthreads();
    for (int st = 128; st > 0; st >>= 1) {
        if (ci < st) red[ci] += red[ci + st];
        __syncthreads();
    }
    if (ci == 0) g_sa[co] = alpha[co] * (red[0] * (1.0f / 2304.0f));
}

// ---------------- prep kernel 2: binarize x (1792 blocks, 15.2KB smem) ----------------
// smem layout: row w (56 rows x 68 words = 272B), 16 blocks of 16B per row.
// block holding ci-group g of row w lives at block index (g ^ (w & 15)).
__global__ void prep_x(const float* __restrict__ x) {
    __shared__ __align__(16) uint32_t sb32[56 * 68];   // 15232B
    const int tid = threadIdx.x;
    const int h   = blockIdx.x % H_;
    const int b   = blockIdx.x / H_;
    const float* xp = x + (size_t)b * CIN * HW + (size_t)h * W_;
    // Stage 1: i -> (c4 = 4-ci group, j = w/4). Loads stay coalesced:
    // runs of 14 lanes with fixed c4 read contiguous 224B per ci row.
    for (int i = tid; i < 896; i += 256) {
        int c4 = i / 14;
        int j  = i - c4 * 14;
        const float* p = xp + (size_t)(4 * c4) * HW + 4 * j;
        float4 v0 = *reinterpret_cast<const float4*>(p);
        float4 v1 = *reinterpret_cast<const float4*>(p + HW);
        float4 v2 = *reinterpret_cast<const float4*>(p + 2 * HW);
        float4 v3 = *reinterpret_cast<const float4*>(p + 3 * HW);
        uint32_t u0 = sign4(v0.x, v1.x, v2.x, v3.x);
        uint32_t u1 = sign4(v0.y, v1.y, v2.y, v3.y);
        uint32_t u2 = sign4(v0.z, v1.z, v2.z, v3.z);
        uint32_t u3 = sign4(v0.w, v1.w, v2.w, v3.w);
        const int g = c4 >> 2, r = c4 & 3;
#pragma unroll
        for (int k = 0; k < 4; k++) {
            int w = 4 * j + k;
            uint32_t uk = (k == 0) ? u0 : (k == 1) ? u1 : (k == 2) ? u2 : u3;
            sb32[w * 68 + 4 * (g ^ (w & 15)) + r] = uk;
        }
    }
    __syncthreads();
    // Stage 2: conflict-free LDS.128 + coalesced STG.128 (same as R13/R15).
    uint8_t* dst = g_xb + (((size_t)b * HP + (h + 1)) * WP + 1) * CIN;
    for (int u = tid; u < 896; u += 256) {
        int w = u >> 4, g = u & 15;
        uint4 v = *reinterpret_cast<const uint4*>(sb32 + w * 68 + 4 * (g ^ (w & 15)));
        *reinterpret_cast<uint4*>(dst + w * 256 + g * 16) = v;
    }
}

// ---------------- main GEMM kernel ----------------
#define NSTG     3
#define A_BYTES  16384                 // 128 M-rows x 128B
#define STG      32768                 // A(16K) + B(16K)
#define GSMEM    (NSTG * STG)          // 98304 B -> 2 CTAs/SM
#define NCHUNK   18                    // 9 taps x 2 ci-chunks of 128

__global__ void __launch_bounds__(256, 2) bconv_gemm(float* __restrict__ out) {
    extern __shared__ char smem[];
    const uint32_t sbase = smem_u32(smem);
    const int tid  = threadIdx.x;
    const int warp = tid >> 5, lane = tid & 31;
    const int mw = warp >> 1;          // 0..3: M rows 32*mw..+31
    const int nw = warp & 1;           // 0..1: N cols 64*nw..+63
    const int bidx = blockIdx.x;
    const int co0  = (bidx & 1) * 128;
    const int m0   = (bidx >> 1) << 7;   // 784*128 = 100352 exact

    const int seg = tid & 7;
    const int rb  = tid >> 3;

    int aoff[4];
#pragma unroll
    for (int k = 0; k < 4; k++) {
        int m = m0 + rb + 32 * k;
        int ib  = m / HW;
        int rem = m - ib * HW;
        int h = rem / W_, w = rem - h * W_;
        aoff[k] = ((ib * HP + h) * WP + w) * CIN + seg * 16;
    }
    int boff[4];
#pragma unroll
    for (int k = 0; k < 4; k++) boff[k] = (co0 + rb + 32 * k) * CIN + seg * 16;
    const uint32_t dstb = rb * 128 + ((seg * 16) ^ ((rb & 7) << 4));

    const int rlo   = lane & 15;
    const int khalf = (lane >> 4) << 4;
    const int swz   = (rlo & 7) << 4;

    int d[2][8][4];
#pragma unroll
    for (int mi = 0; mi < 2; mi++)
#pragma unroll
        for (int ni = 0; ni < 8; ni++)
#pragma unroll
            for (int j = 0; j < 4; j++) d[mi][ni][j] = 0;

    auto load_chunk = [&](int chunk, int stage) {
        const int t  = chunk >> 1;
        const int cc = (chunk & 1) << 7;
        const int kh = t / 3, kw = t - kh * 3;
        const int toffA = (kh * WP + kw) * CIN + cc;
        const int toffB = t * (COUT * CIN) + cc;
        const uint32_t stgA = sbase + stage * STG + dstb;
        const uint32_t stgB = stgA + A_BYTES;
#pragma unroll
        for (int k = 0; k < 4; k++)
            CP16(stgA + k * 4096, (const char*)g_xb + aoff[k] + toffA);
#pragma unroll
        for (int k = 0; k < 4; k++)
            CP16(stgB + k * 4096, (const char*)g_wb + boff[k] + toffB);
    };

    load_chunk(0, 0); CP_COMMIT();
    load_chunk(1, 1); CP_COMMIT();

    const int rowA0 = 32 * mw + rlo;
    const int rowB0 = 64 * nw + rlo;

    int stage = 2;
    for (int i = 0; i < NCHUNK; i++) {
        CP_WAIT(1);
        __syncthreads();
        if (i + 2 < NCHUNK) load_chunk(i + 2, stage);
        CP_COMMIT();

        const int cur = (stage == 2) ? 0 : stage + 1;   // = i % 3
        stage = cur;
        const uint32_t stgA = sbase + cur * STG;
        const uint32_t stgB = stgA + A_BYTES;
#pragma unroll
        for (int ks = 0; ks < 4; ks++) {
            const int kb = ks * 32 + khalf;
            uint32_t a[2][4], bf[4][4];
            LDSM4(a[0], stgA + rowA0 * 128 + (kb ^ swz));
            LDSM4(a[1], stgA + (rowA0 + 16) * 128 + (kb ^ swz));
#pragma unroll
            for (int np = 0; np < 4; np++)
                LDSM4(bf[np], stgB + (rowB0 + 16 * np) * 128 + (kb ^ swz));
#pragma unroll
            for (int np = 0; np < 4; np++) {
                MMAI(d[0][2 * np],     a[0], bf[np][0], bf[np][2]);
                MMAI(d[0][2 * np + 1], a[0], bf[np][1], bf[np][3]);
                MMAI(d[1][2 * np],     a[1], bf[np][0], bf[np][2]);
                MMAI(d[1][2 * np + 1], a[1], bf[np][1], bf[np][3]);
            }
        }
    }

    CP_WAIT(0);
    __syncthreads();

    // ---------------- epilogue (table-free) ----------------
    int* buf = (int*)smem;                         // 64 cl x 128 rows = 32KB
    const int r   = tid & 127;
    const int clb = tid >> 7;
    int soff;
    {
        int m   = m0 + r;
        int ib  = m / HW;
        int rem = m - ib * HW;
        soff = ib * (COUT * HW) + rem;
    }
    const int q  = lane & 3;
    const int rr = lane >> 2;
#pragma unroll 1
    for (int hh = 0; hh < 2; hh++) {
        if (nw == hh) {
#pragma unroll
            for (int mi = 0; mi < 2; mi++)
#pragma unroll
                for (int ni = 0; ni < 8; ni++) {
                    int cl  = 8 * ni + 2 * q;
                    int row = 32 * mw + 16 * mi + rr;
                    buf[cl * 128 + row]           = d[mi][ni][0];
                    buf[(cl + 1) * 128 + row]     = d[mi][ni][1];
                    buf[cl * 128 + row + 8]       = d[mi][ni][2];
                    buf[(cl + 1) * 128 + row + 8] = d[mi][ni][3];
                }
        }
        __syncthreads();
#pragma unroll 4
        for (int it = 0; it < 32; it++) {
            int cl = clb + 2 * it;
            int co = co0 + hh * 64 + cl;
            out[soff + co * HW] = (float)buf[cl * 128 + r] * __ldg(&g_sa[co]);
        }
        __syncthreads();
    }
}

// ---------------- launch ----------------
extern "C" void kernel_launch(void* const* d_in, const int* in_sizes, int n_in,
                              void* d_out, int out_size) {
    const float* x     = (const float*)d_in[0];  // [32,256,56,56]
    const float* wts   = (const float*)d_in[1];  // [4,256,256,3,3]
    const float* rv    = (const float*)d_in[2];  // [5]
    const float* alpha = (const float*)d_in[3];  // [256]
    float* out = (float*)d_out;

    cudaFuncSetAttribute(bconv_gemm, cudaFuncAttributeMaxDynamicSharedMemorySize, GSMEM);

    prep_x<<<B_ * H_, 256>>>(x);
    prep_w<<<COUT, 256>>>(wts, rv, alpha);
    bconv_gemm<<<784 * 2, 256, GSMEM>>>(out);
}

// round 17
// speedup vs baseline: 1.1382x; 1.0283x over previous
#include <cuda_runtime.h>
#include <cstdint>

// ============================================================
// BinarizeConv2d: out = conv3x3(sign(x), sign(mix(W))) * scale * alpha
// Implicit GEMM, mma.sync m16n8k32 s8s8s32 (exact for ±1), sm_100.
// R17 = R16 GEMM mainloop + single-phase 64KB epilogue (was 2
//       serialized 32KB phases) + prep merged into ONE kernel:
//       x-blocks (15KB smem) first, low-smem weight blocks last
//       (prep_w tail hidden behind prep_x; one launch saved).
// ============================================================

#define B_   32
#define CIN  256
#define COUT 256
#define H_   56
#define W_   56
#define HP   58
#define WP   58
#define HW   3136      // 56*56

// int8 encodings of {+1,-1,0}: 0x01, 0xFF, 0x00
__device__ uint8_t g_xb[(size_t)B_ * HP * WP * CIN];  // sign(x), NHWC padded (borders stay 0)
__device__ uint8_t g_wb[9 * COUT * CIN];              // sign(real_w) [tap][co][ci]
__device__ float   g_sa[COUT];                        // alpha * scale

// ---------------- PTX helpers ----------------
__device__ __forceinline__ uint32_t smem_u32(const void* p) {
    uint32_t a;
    asm("{ .reg .u64 t; cvta.to.shared.u64 t, %1; cvt.u32.u64 %0, t; }" : "=r"(a) : "l"(p));
    return a;
}
#define CP16(d, s)   asm volatile("cp.async.cg.shared.global [%0], [%1], 16;" :: "r"(d), "l"(s) : "memory")
#define CP_COMMIT()  asm volatile("cp.async.commit_group;" ::: "memory")
#define CP_WAIT(n)   asm volatile("cp.async.wait_group %0;" :: "n"(n) : "memory")

#define LDSM4(r, a)                                                          \
    asm volatile("ldmatrix.sync.aligned.m8n8.x4.shared.b16 {%0,%1,%2,%3}, [%4];" \
        : "=r"((r)[0]), "=r"((r)[1]), "=r"((r)[2]), "=r"((r)[3]) : "r"(a))

#define MMAI(d, a, b0, b1)                                                   \
    asm volatile("mma.sync.aligned.m16n8k32.row.col.s32.s8.s8.s32 "          \
        "{%0,%1,%2,%3}, {%4,%5,%6,%7}, {%8,%9}, {%0,%1,%2,%3};"              \
        : "+r"((d)[0]), "+r"((d)[1]), "+r"((d)[2]), "+r"((d)[3])             \
        : "r"((a)[0]), "r"((a)[1]), "r"((a)[2]), "r"((a)[3]),                \
          "r"(b0), "r"(b1))

__device__ __forceinline__ uint8_t sign_s8(float v) {
    return (v > 0.f) ? 0x01 : ((v < 0.f) ? 0xFF : 0x00);
}
__device__ __forceinline__ uint32_t sign4(float a, float b, float c, float d) {
    return (uint32_t)sign_s8(a) | ((uint32_t)sign_s8(b) << 8) |
           ((uint32_t)sign_s8(c) << 16) | ((uint32_t)sign_s8(d) << 24);
}

// ---------------- merged prep kernel (15.2KB smem for ALL blocks) ----------------
// blocks [0,1792):          binarize x (one (b,h) row each) — scheduled first
// blocks [1792,1792+256):   weight mix/sign/scale (direct reads, 1KB red overlay)
#define NXBLK (B_ * H_)   // 1792

__global__ void prep_all(const float* __restrict__ Wt, const float* __restrict__ RV,
                         const float* __restrict__ alpha, const float* __restrict__ x) {
    __shared__ __align__(16) uint32_t sb32[56 * 68];   // 15232B (x) / red overlay (w)
    const int tid = threadIdx.x;
    if (blockIdx.x < NXBLK) {
        // ---- binarize x: 4ci x 4w per thread, packed STS.32 + XOR swizzle ----
        const int h = blockIdx.x % H_;
        const int b = blockIdx.x / H_;
        const float* xp = x + (size_t)b * CIN * HW + (size_t)h * W_;
        for (int i = tid; i < 896; i += 256) {
            int c4 = i / 14;
            int j  = i - c4 * 14;
            const float* p = xp + (size_t)(4 * c4) * HW + 4 * j;
            float4 v0 = *reinterpret_cast<const float4*>(p);
            float4 v1 = *reinterpret_cast<const float4*>(p + HW);
            float4 v2 = *reinterpret_cast<const float4*>(p + 2 * HW);
            float4 v3 = *reinterpret_cast<const float4*>(p + 3 * HW);
            uint32_t u0 = sign4(v0.x, v1.x, v2.x, v3.x);
            uint32_t u1 = sign4(v0.y, v1.y, v2.y, v3.y);
            uint32_t u2 = sign4(v0.z, v1.z, v2.z, v3.z);
            uint32_t u3 = sign4(v0.w, v1.w, v2.w, v3.w);
            const int g = c4 >> 2, r = c4 & 3;
#pragma unroll
            for (int k = 0; k < 4; k++) {
                int w = 4 * j + k;
                uint32_t uk = (k == 0) ? u0 : (k == 1) ? u1 : (k == 2) ? u2 : u3;
                sb32[w * 68 + 4 * (g ^ (w & 15)) + r] = uk;
            }
        }
        __syncthreads();
        uint8_t* dst = g_xb + (((size_t)b * HP + (h + 1)) * WP + 1) * CIN;
        for (int u = tid; u < 896; u += 256) {
            int w = u >> 4, g = u & 15;
            uint4 v = *reinterpret_cast<const uint4*>(sb32 + w * 68 + 4 * (g ^ (w & 15)));
            *reinterpret_cast<uint4*>(dst + w * 256 + g * 16) = v;
        }
    } else {
        // ---- weights: direct (uncoalesced) reads; tail hidden behind x-blocks ----
        float* red = (float*)sb32;                  // 1KB overlay
        const int co = blockIdx.x - NXBLK, ci = tid;
        const float r0 = RV[0], r1 = RV[1], r2 = RV[2], r3 = RV[3];
        const size_t ks = (size_t)COUT * CIN * 9;
        const float* w0 = Wt + ((size_t)co * CIN + ci) * 9;
        float acc = 0.f;
#pragma unroll
        for (int t = 0; t < 9; t++) {
            float rw = r0 * w0[t] + r1 * w0[t + ks] + r2 * w0[t + 2 * ks] + r3 * w0[t + 3 * ks];
            acc += fabsf(rw);
            g_wb[((size_t)t * COUT + co) * CIN + ci] = sign_s8(rw);
        }
        red[ci] = acc;
        __syncthreads();
        for (int st = 128; st > 0; st >>= 1) {
            if (ci < st) red[ci] += red[ci + st];
            __syncthreads();
        }
        if (ci == 0) g_sa[co] = alpha[co] * (red[0] * (1.0f / 2304.0f));
    }
}

// ---------------- main GEMM kernel ----------------
#define NSTG     3
#define A_BYTES  16384                 // 128 M-rows x 128B
#define STG      32768                 // A(16K) + B(16K)
#define GSMEM    (NSTG * STG)          // 98304 B -> 2 CTAs/SM
#define NCHUNK   18                    // 9 taps x 2 ci-chunks of 128

__global__ void __launch_bounds__(256, 2) bconv_gemm(float* __restrict__ out) {
    extern __shared__ char smem[];
    const uint32_t sbase = smem_u32(smem);
    const int tid  = threadIdx.x;
    const int warp = tid >> 5, lane = tid & 31;
    const int mw = warp >> 1;          // 0..3: M rows 32*mw..+31
    const int nw = warp & 1;           // 0..1: N cols 64*nw..+63
    const int bidx = blockIdx.x;
    const int co0  = (bidx & 1) * 128;
    const int m0   = (bidx >> 1) << 7;   // 784*128 = 100352 exact

    const int seg = tid & 7;
    const int rb  = tid >> 3;

    int aoff[4];
#pragma unroll
    for (int k = 0; k < 4; k++) {
        int m = m0 + rb + 32 * k;
        int ib  = m / HW;
        int rem = m - ib * HW;
        int h = rem / W_, w = rem - h * W_;
        aoff[k] = ((ib * HP + h) * WP + w) * CIN + seg * 16;
    }
    int boff[4];
#pragma unroll
    for (int k = 0; k < 4; k++) boff[k] = (co0 + rb + 32 * k) * CIN + seg * 16;
    const uint32_t dstb = rb * 128 + ((seg * 16) ^ ((rb & 7) << 4));

    const int rlo   = lane & 15;
    const int khalf = (lane >> 4) << 4;
    const int swz   = (rlo & 7) << 4;

    int d[2][8][4];
#pragma unroll
    for (int mi = 0; mi < 2; mi++)
#pragma unroll
        for (int ni = 0; ni < 8; ni++)
#pragma unroll
            for (int j = 0; j < 4; j++) d[mi][ni][j] = 0;

    auto load_chunk = [&](int chunk, int stage) {
        const int t  = chunk >> 1;
        const int cc = (chunk & 1) << 7;
        const int kh = t / 3, kw = t - kh * 3;
        const int toffA = (kh * WP + kw) * CIN + cc;
        const int toffB = t * (COUT * CIN) + cc;
        const uint32_t stgA = sbase + stage * STG + dstb;
        const uint32_t stgB = stgA + A_BYTES;
#pragma unroll
        for (int k = 0; k < 4; k++)
            CP16(stgA + k * 4096, (const char*)g_xb + aoff[k] + toffA);
#pragma unroll
        for (int k = 0; k < 4; k++)
            CP16(stgB + k * 4096, (const char*)g_wb + boff[k] + toffB);
    };

    load_chunk(0, 0); CP_COMMIT();
    load_chunk(1, 1); CP_COMMIT();

    const int rowA0 = 32 * mw + rlo;
    const int rowB0 = 64 * nw + rlo;

    int stage = 2;
    for (int i = 0; i < NCHUNK; i++) {
        CP_WAIT(1);
        __syncthreads();
        if (i + 2 < NCHUNK) load_chunk(i + 2, stage);
        CP_COMMIT();

        const int cur = (stage == 2) ? 0 : stage + 1;   // = i % 3
        stage = cur;
        const uint32_t stgA = sbase + cur * STG;
        const uint32_t stgB = stgA + A_BYTES;
#pragma unroll
        for (int ks = 0; ks < 4; ks++) {
            const int kb = ks * 32 + khalf;
            uint32_t a[2][4], bf[4][4];
            LDSM4(a[0], stgA + rowA0 * 128 + (kb ^ swz));
            LDSM4(a[1], stgA + (rowA0 + 16) * 128 + (kb ^ swz));
#pragma unroll
            for (int np = 0; np < 4; np++)
                LDSM4(bf[np], stgB + (rowB0 + 16 * np) * 128 + (kb ^ swz));
#pragma unroll
            for (int np = 0; np < 4; np++) {
                MMAI(d[0][2 * np],     a[0], bf[np][0], bf[np][2]);
                MMAI(d[0][2 * np + 1], a[0], bf[np][1], bf[np][3]);
                MMAI(d[1][2 * np],     a[1], bf[np][0], bf[np][2]);
                MMAI(d[1][2 * np + 1], a[1], bf[np][1], bf[np][3]);
            }
        }
    }

    CP_WAIT(0);
    __syncthreads();

    // ---------------- epilogue: single phase, 64KB buffer ----------------
    // All 8 warps write their 128x64 halves simultaneously (disjoint cl
    // ranges via nw), one barrier, then 64 fully-coalesced store rounds.
    int* buf = (int*)smem;                         // 128 cl x 128 rows = 64KB
    const int q  = lane & 3;
    const int rr = lane >> 2;
#pragma unroll
    for (int mi = 0; mi < 2; mi++)
#pragma unroll
        for (int ni = 0; ni < 8; ni++) {
            int cl  = 64 * nw + 8 * ni + 2 * q;
            int row = 32 * mw + 16 * mi + rr;
            buf[cl * 128 + row]           = d[mi][ni][0];
            buf[(cl + 1) * 128 + row]     = d[mi][ni][1];
            buf[cl * 128 + row + 8]       = d[mi][ni][2];
            buf[(cl + 1) * 128 + row + 8] = d[mi][ni][3];
        }
    __syncthreads();
    const int r   = tid & 127;
    const int clb = tid >> 7;
    int soff;
    {
        int m   = m0 + r;
        int ib  = m / HW;
        int rem = m - ib * HW;
        soff = ib * (COUT * HW) + rem;
    }
#pragma unroll 4
    for (int it = 0; it < 64; it++) {
        int cl = clb + 2 * it;
        int co = co0 + cl;
        out[soff + co * HW] = (float)buf[cl * 128 + r] * __ldg(&g_sa[co]);
    }
}

// ---------------- launch ----------------
extern "C" void kernel_launch(void* const* d_in, const int* in_sizes, int n_in,
                              void* d_out, int out_size) {
    const float* x     = (const float*)d_in[0];  // [32,256,56,56]
    const float* wts   = (const float*)d_in[1];  // [4,256,256,3,3]
    const float* rv    = (const float*)d_in[2];  // [5]
    const float* alpha = (const float*)d_in[3];  // [256]
    float* out = (float*)d_out;

    cudaFuncSetAttribute(bconv_gemm, cudaFuncAttributeMaxDynamicSharedMemorySize, GSMEM);

    prep_all<<<NXBLK + COUT, 256>>>(wts, rv, alpha, x);
    bconv_gemm<<<784 * 2, 256, GSMEM>>>(out);
}